// round 14
// baseline (speedup 1.0000x reference)
#include <cuda_runtime.h>
#include <cuda_fp16.h>
#include <math.h>
#include <stdint.h>

#define S_ 512
#define R_ 128
#define C_ 256
#define H_ 8
#define DH_ 32
#define M_ (R_*S_)
#define EPSV 1e-5f
#define QSCALE 0.2550348923f   // (1/sqrt(32)) * log2(e), folded into q

__device__ __align__(256) __half g_xn16[(size_t)M_ * C_];   // ln out, [r][s][c]
__device__ __align__(256) __half g_q16[(size_t)M_ * C_];    // pre-scaled by QSCALE
__device__ __align__(256) __half g_k16[(size_t)M_ * C_];
__device__ __align__(256) __half g_v16[(size_t)M_ * C_];    // [r][s][h*32+dh]
__device__ __align__(256) __half g_oat16[(size_t)M_ * C_];  // gated attn out
__device__ __align__(256) __half g_gate16[(size_t)M_ * C_]; // sigmoid gate, fp16
__device__ __align__(256) __half g_w16[5 * 65536];          // W^T (n-major) fp16

// ---------------------------------------------------------------------------
// helpers
// ---------------------------------------------------------------------------
__device__ __forceinline__ void mma_f16(float* c, const uint32_t* a, const uint32_t* b) {
    asm volatile(
        "mma.sync.aligned.m16n8k16.row.col.f32.f16.f16.f32 "
        "{%0,%1,%2,%3}, {%4,%5,%6,%7}, {%8,%9}, {%0,%1,%2,%3};\n"
        : "+f"(c[0]), "+f"(c[1]), "+f"(c[2]), "+f"(c[3])
        : "r"(a[0]), "r"(a[1]), "r"(a[2]), "r"(a[3]), "r"(b[0]), "r"(b[1]));
}
__device__ __forceinline__ void ldsm4(uint32_t* r, uint32_t addr) {
    asm volatile("ldmatrix.sync.aligned.m8n8.x4.shared.b16 {%0,%1,%2,%3}, [%4];"
        : "=r"(r[0]), "=r"(r[1]), "=r"(r[2]), "=r"(r[3]) : "r"(addr));
}
__device__ __forceinline__ void ldsm4t(uint32_t* r, uint32_t addr) {
    asm volatile("ldmatrix.sync.aligned.m8n8.x4.trans.shared.b16 {%0,%1,%2,%3}, [%4];"
        : "=r"(r[0]), "=r"(r[1]), "=r"(r[2]), "=r"(r[3]) : "r"(addr));
}
__device__ __forceinline__ uint32_t packh2(float lo, float hi) {
    __half2 h = __floats2half2_rn(lo, hi);
    return *reinterpret_cast<uint32_t*>(&h);
}
__device__ __forceinline__ uint32_t h2ex2(uint32_t x) {
    uint32_t r; asm("ex2.approx.f16x2 %0, %1;" : "=r"(r) : "r"(x)); return r;
}
__device__ __forceinline__ uint32_t smaddr(const void* p) {
    return (uint32_t)__cvta_generic_to_shared(p);
}
__device__ __forceinline__ void cpa16(uint32_t s, const void* g) {
    asm volatile("cp.async.cg.shared.global [%0], [%1], 16;\n" :: "r"(s), "l"(g));
}
__device__ __forceinline__ void cpa_commit() { asm volatile("cp.async.commit_group;\n"); }
template<int N> __device__ __forceinline__ void cpa_wait() {
    asm volatile("cp.async.wait_group %0;\n" :: "n"(N));
}

// ---------------------------------------------------------------------------
// Weight prep: transpose 5 weight matrices to [n][k] fp16
// ---------------------------------------------------------------------------
__global__ __launch_bounds__(256) void prep_w(const float* __restrict__ wq,
                                              const float* __restrict__ wk,
                                              const float* __restrict__ wv,
                                              const float* __restrict__ wg,
                                              const float* __restrict__ wf) {
    __shared__ float tile[32][33];
    const float* s;
    switch (blockIdx.z) {
        case 0: s = wq; break;
        case 1: s = wk; break;
        case 2: s = wv; break;
        case 3: s = wg; break;
        default: s = wf; break;
    }
    int km = blockIdx.x * 32, nm = blockIdx.y * 32;
    int t = threadIdx.x, tr = t >> 5, tc = t & 31;
    #pragma unroll
    for (int p = 0; p < 4; p++)
        tile[tr + p * 8][tc] = s[(size_t)(km + tr + p * 8) * C_ + nm + tc];
    __syncthreads();
    #pragma unroll
    for (int p = 0; p < 4; p++) {
        int n = tr + p * 8;
        g_w16[(size_t)blockIdx.z * 65536 + (size_t)(nm + n) * C_ + km + tc] =
            __float2half_rn(tile[tc][n]);
    }
}

// ---------------------------------------------------------------------------
// LayerNorm over C + transpose [s][r][c] -> [r][s][c], store fp16
// ---------------------------------------------------------------------------
__global__ __launch_bounds__(256) void ln_kernel(const float* __restrict__ x,
                                                 const float* __restrict__ w,
                                                 const float* __restrict__ b) {
    int sr = blockIdx.x;
    int s = sr >> 7;
    int r = sr & 127;
    int t = threadIdx.x;
    float v = x[(size_t)sr * C_ + t];
    float sum = v, sq = v * v;
    #pragma unroll
    for (int o = 16; o > 0; o >>= 1) {
        sum += __shfl_xor_sync(0xffffffffu, sum, o);
        sq  += __shfl_xor_sync(0xffffffffu, sq,  o);
    }
    __shared__ float rs[8], rq[8];
    __shared__ float s_mu, s_rstd;
    int wid = t >> 5, lid = t & 31;
    if (lid == 0) { rs[wid] = sum; rq[wid] = sq; }
    __syncthreads();
    if (t == 0) {
        float a = 0.f, c2 = 0.f;
        #pragma unroll
        for (int i = 0; i < 8; i++) { a += rs[i]; c2 += rq[i]; }
        float mu  = a * (1.0f / C_);
        float var = c2 * (1.0f / C_) - mu * mu;
        s_mu = mu; s_rstd = rsqrtf(var + EPSV);
    }
    __syncthreads();
    g_xn16[((size_t)r * S_ + s) * C_ + t] =
        __float2half_rn((v - s_mu) * s_rstd * w[t] + b[t]);
}

// ---------------------------------------------------------------------------
// fp16 GEMM, 3-stage cp.async, ldmatrix fragments:
// g_xn16[M_,256] @ W^T -> q|k|v (fp16) / gate (fp16). 128x128, BK=32, 8 warps.
// q is pre-scaled by QSCALE so attention logits are already in log2 domain.
// ---------------------------------------------------------------------------
#define ASH 5120                     // 128*40 halves per stage
#define GEMM_SMEM (3 * 2 * ASH * 2)  // 61440 bytes

__global__ __launch_bounds__(256) void proj_gemm(const float* __restrict__ bg) {
    extern __shared__ __half smh[];
    __half* As = smh;                // [3][128][40]
    __half* Bs = smh + 3 * ASH;      // [3][128][40]
    const int tid = threadIdx.x;
    const int wid = tid >> 5, lane = tid & 31, g = lane >> 2, tig = lane & 3;
    const int warp_m = wid & 3, warp_n = wid >> 2;
    const int lm = lane >> 3, lr = lane & 7;
    const uint32_t aofs = (((lm & 1) * 8 + lr) * 40 + (lm >> 1) * 8) * 2;
    const uint32_t bofs = (((lm >> 1) * 8 + lr) * 40 + (lm & 1) * 8) * 2;
    const int m0 = blockIdx.x * 128;
    const int y = blockIdx.y;
    const int widx = y >> 1;
    const __half* Wp = g_w16 + (size_t)widx * 65536;
    const int n0w = (y & 1) * 128;

    float acc[2][8][4] = {};

    auto issue = [&](int st, int k0) {
        #pragma unroll
        for (int p = 0; p < 2; p++) {
            int idx = p * 256 + tid;
            int row = idx >> 2, c = idx & 3;
            cpa16(smaddr(&As[st * ASH + row * 40 + c * 8]),
                  &g_xn16[(size_t)(m0 + row) * C_ + k0 + c * 8]);
            cpa16(smaddr(&Bs[st * ASH + row * 40 + c * 8]),
                  &Wp[(size_t)(n0w + row) * C_ + k0 + c * 8]);
        }
        cpa_commit();
    };
    issue(0, 0); issue(1, 32);

    for (int it = 0; it < 8; it++) {
        if (it < 7) cpa_wait<1>(); else cpa_wait<0>();
        __syncthreads();
        if (it < 6) issue((it + 2) % 3, (it + 2) * 32);
        uint32_t ab = smaddr(&As[(it % 3) * ASH]) + warp_m * 32 * 80;
        uint32_t bb = smaddr(&Bs[(it % 3) * ASH]) + warp_n * 64 * 80;
        #pragma unroll
        for (int kc = 0; kc < 2; kc++) {
            uint32_t a[2][4], bf[8][2], r4[4];
            ldsm4(a[0], ab + aofs + kc * 32);
            ldsm4(a[1], ab + 16 * 80 + aofs + kc * 32);
            #pragma unroll
            for (int q4 = 0; q4 < 4; q4++) {
                ldsm4(r4, bb + q4 * 16 * 80 + bofs + kc * 32);
                bf[q4 * 2][0] = r4[0]; bf[q4 * 2][1] = r4[1];
                bf[q4 * 2 + 1][0] = r4[2]; bf[q4 * 2 + 1][1] = r4[3];
            }
            #pragma unroll
            for (int mi = 0; mi < 2; mi++)
                #pragma unroll
                for (int ni = 0; ni < 8; ni++)
                    mma_f16(acc[mi][ni], a[mi], bf[ni]);
        }
    }

    __half* dsth = (widx == 0) ? g_q16 : (widx == 1) ? g_k16 : g_v16;
    #pragma unroll
    for (int mi = 0; mi < 2; mi++)
        #pragma unroll
        for (int rh = 0; rh < 2; rh++) {
            int m = m0 + warp_m * 32 + mi * 16 + rh * 8 + g;
            #pragma unroll
            for (int ni = 0; ni < 8; ni++) {
                int ng = n0w + warp_n * 64 + ni * 8 + 2 * tig;
                float vx = acc[mi][ni][rh * 2], vy = acc[mi][ni][rh * 2 + 1];
                if (widx == 3) {
                    float gx = 1.f / (1.f + __expf(-(vx + bg[ng])));
                    float gy = 1.f / (1.f + __expf(-(vy + bg[ng + 1])));
                    *(uint32_t*)&g_gate16[(size_t)m * C_ + ng] = packh2(gx, gy);
                } else {
                    if (widx == 0) { vx *= QSCALE; vy *= QSCALE; }
                    *(uint32_t*)&dsth[(size_t)m * C_ + ng] = packh2(vx, vy);
                }
            }
        }
}

// ---------------------------------------------------------------------------
// Flash attention, fp16 m16n8k16. 256 queries/block, 8 warps, 4-stage
// cp.async K/V ring (3 tiles in flight). Max-free log2-domain softmax via
// ex2.approx.f16x2; P in registers; V^T fragments via ldmatrix.trans.
// ---------------------------------------------------------------------------
#define KVH 1280    // 32*40 halves per stage
#define QH  10240   // 256*40 halves
#define ATTN_SMEM ((QH + 8 * KVH) * 2)   // 40960 bytes

__global__ __launch_bounds__(256) void attn_mma() {
    extern __shared__ __half smh[];
    __half* Qs = smh;                 // [256][40]
    __half* Ks = smh + QH;            // [4][32][40]  rows j, cols dh
    __half* Vs = Ks + 4 * KVH;        // [4][32][40]  rows j, cols dh
    const int qt = blockIdx.x;        // 0..1
    const int h  = blockIdx.y;
    const int r  = blockIdx.z;
    const int tid = threadIdx.x, wid = tid >> 5, lane = tid & 31;
    const int g = lane >> 2, tig = lane & 3;
    const int lm = lane >> 3, lr = lane & 7;
    const uint32_t kofs = (((lm >> 1) * 8 + lr) * 40 + (lm & 1) * 8) * 2;
    const uint32_t vofs = (((lm & 1) * 8 + lr) * 40 + (lm >> 1) * 8) * 2;
    const size_t rbase = (size_t)r * S_;

    // 256 threads: tid<128 loads K tile (128 x 16B), tid>=128 loads V tile.
    const int irow = (tid & 127) >> 2, ic = tid & 3;
    auto issue = [&](int st, int j0) {
        if (tid < 128)
            cpa16(smaddr(&Ks[st * KVH + irow * 40 + ic * 8]),
                  &g_k16[(rbase + j0 + irow) * C_ + h * 32 + ic * 8]);
        else
            cpa16(smaddr(&Vs[st * KVH + irow * 40 + ic * 8]),
                  &g_v16[(rbase + j0 + irow) * C_ + h * 32 + ic * 8]);
        cpa_commit();
    };
    issue(0, 0); issue(1, 32); issue(2, 64);

    // Stage Q (256 rows), hoist fragments to registers
    #pragma unroll
    for (int p = 0; p < 4; p++) {
        int linear = p * 256 + tid;
        int row = linear >> 2, c = linear & 3;
        *(uint4*)&Qs[row * 40 + c * 8] =
            *(const uint4*)&g_q16[(rbase + qt * 256 + row) * C_ + h * 32 + c * 8];
    }
    __syncthreads();
    uint32_t qf[2][2][4];                      // [kc][mi]
    {
        uint32_t qb = smaddr(Qs) + wid * 32 * 80;
        const uint32_t qaofs = (((lm & 1) * 8 + lr) * 40 + (lm >> 1) * 8) * 2;
        #pragma unroll
        for (int kc = 0; kc < 2; kc++) {
            ldsm4(qf[kc][0], qb + qaofs + kc * 32);
            ldsm4(qf[kc][1], qb + 16 * 80 + qaofs + kc * 32);
        }
    }

    float lpart[2][2] = {};
    float oacc[2][4][4] = {};
    const uint32_t ksb = smaddr(Ks), vsb = smaddr(Vs);

    for (int t = 0; t < 16; t++) {
        if (t < 14) cpa_wait<2>(); else if (t == 14) cpa_wait<1>(); else cpa_wait<0>();
        __syncthreads();
        if (t < 13) issue((t + 3) & 3, (t + 3) * 32);
        uint32_t kb = ksb + (t & 3) * (KVH * 2);
        uint32_t vb = vsb + (t & 3) * (KVH * 2);

        // S = Q . K^T  (32q x 32k per warp); sacc is already log2-domain
        float sacc[2][4][4] = {};
        #pragma unroll
        for (int kc = 0; kc < 2; kc++) {
            uint32_t bk[4][2], r4[4];
            ldsm4(r4, kb + kofs + kc * 32);
            bk[0][0] = r4[0]; bk[0][1] = r4[1]; bk[1][0] = r4[2]; bk[1][1] = r4[3];
            ldsm4(r4, kb + kofs + kc * 32 + 16 * 80);
            bk[2][0] = r4[0]; bk[2][1] = r4[1]; bk[3][0] = r4[2]; bk[3][1] = r4[3];
            #pragma unroll
            for (int mi = 0; mi < 2; mi++)
                #pragma unroll
                for (int ni = 0; ni < 4; ni++)
                    mma_f16(sacc[mi][ni], qf[kc][mi], bk[ni]);
        }

        // Max-free softmax: p = 2^x via ex2.approx.f16x2, straight into A frags.
        uint32_t pa[2][2][4];                  // [kc][mi]
        #pragma unroll
        for (int mi = 0; mi < 2; mi++) {
            __half2 tl0 = __float2half2_rn(0.f);
            __half2 tl1 = __float2half2_rn(0.f);
            #pragma unroll
            for (int ni = 0; ni < 4; ni++) {
                int kc = ni >> 1, i0 = (ni & 1) * 2;
                uint32_t p0 = h2ex2(packh2(sacc[mi][ni][0], sacc[mi][ni][1]));
                uint32_t p1 = h2ex2(packh2(sacc[mi][ni][2], sacc[mi][ni][3]));
                pa[kc][mi][i0]     = p0;
                pa[kc][mi][i0 + 1] = p1;
                tl0 = __hadd2(tl0, *reinterpret_cast<__half2*>(&p0));
                tl1 = __hadd2(tl1, *reinterpret_cast<__half2*>(&p1));
            }
            float2 f0 = __half22float2(tl0);
            float2 f1 = __half22float2(tl1);
            lpart[mi][0] += f0.x + f0.y;
            lpart[mi][1] += f1.x + f1.y;
        }

        // O += P . V   — V^T fragments via ldmatrix.trans from [j][dh] tile
        #pragma unroll
        for (int kc = 0; kc < 2; kc++) {
            uint32_t bv[4][2], r4[4];
            ldsm4t(r4, vb + vofs + kc * 1280);
            bv[0][0] = r4[0]; bv[0][1] = r4[1]; bv[1][0] = r4[2]; bv[1][1] = r4[3];
            ldsm4t(r4, vb + vofs + kc * 1280 + 32);
            bv[2][0] = r4[0]; bv[2][1] = r4[1]; bv[3][0] = r4[2]; bv[3][1] = r4[3];
            #pragma unroll
            for (int mi = 0; mi < 2; mi++)
                #pragma unroll
                for (int ni = 0; ni < 4; ni++)
                    mma_f16(oacc[mi][ni], pa[kc][mi], bv[ni]);
        }
    }

    #pragma unroll
    for (int mi = 0; mi < 2; mi++)
        #pragma unroll
        for (int rh = 0; rh < 2; rh++) {
            float ts = lpart[mi][rh];
            ts += __shfl_xor_sync(0xffffffffu, ts, 1);
            ts += __shfl_xor_sync(0xffffffffu, ts, 2);
            float inv = 1.f / ts;
            int q = qt * 256 + wid * 32 + mi * 16 + rh * 8 + g;
            #pragma unroll
            for (int ni = 0; ni < 4; ni++) {
                int n = ni * 8 + 2 * tig;
                uint32_t gbits = *(const uint32_t*)&g_gate16[(rbase + q) * C_ + h * 32 + n];
                float2 gg = __half22float2(*reinterpret_cast<__half2*>(&gbits));
                *(uint32_t*)&g_oat16[(rbase + q) * C_ + h * 32 + n] =
                    packh2(oacc[mi][ni][rh * 2] * inv * gg.x,
                           oacc[mi][ni][rh * 2 + 1] * inv * gg.y);
            }
        }
}

// ---------------------------------------------------------------------------
// fp16 GEMM: g_oat16 @ wf^T + bf, transposed store to out[s][r][c]
// ---------------------------------------------------------------------------
__global__ __launch_bounds__(256) void out_gemm(const float* __restrict__ bfv,
                                                float* __restrict__ out) {
    extern __shared__ __half smh[];
    __half* As = smh;
    __half* Bs = smh + 3 * ASH;
    const int tid = threadIdx.x;
    const int wid = tid >> 5, lane = tid & 31, g = lane >> 2, tig = lane & 3;
    const int warp_m = wid & 3, warp_n = wid >> 2;
    const int lm = lane >> 3, lr = lane & 7;
    const uint32_t aofs = (((lm & 1) * 8 + lr) * 40 + (lm >> 1) * 8) * 2;
    const uint32_t bofs = (((lm >> 1) * 8 + lr) * 40 + (lm & 1) * 8) * 2;
    const int m0 = blockIdx.x * 128;
    const int n0 = blockIdx.y * 128;
    const __half* Wp = g_w16 + (size_t)4 * 65536;

    float acc[2][8][4] = {};

    auto issue = [&](int st, int k0) {
        #pragma unroll
        for (int p = 0; p < 2; p++) {
            int idx = p * 256 + tid;
            int row = idx >> 2, c = idx & 3;
            cpa16(smaddr(&As[st * ASH + row * 40 + c * 8]),
                  &g_oat16[(size_t)(m0 + row) * C_ + k0 + c * 8]);
            cpa16(smaddr(&Bs[st * ASH + row * 40 + c * 8]),
                  &Wp[(size_t)(n0 + row) * C_ + k0 + c * 8]);
        }
        cpa_commit();
    };
    issue(0, 0); issue(1, 32);

    for (int it = 0; it < 8; it++) {
        if (it < 7) cpa_wait<1>(); else cpa_wait<0>();
        __syncthreads();
        if (it < 6) issue((it + 2) % 3, (it + 2) * 32);
        uint32_t ab = smaddr(&As[(it % 3) * ASH]) + warp_m * 32 * 80;
        uint32_t bb = smaddr(&Bs[(it % 3) * ASH]) + warp_n * 64 * 80;
        #pragma unroll
        for (int kc = 0; kc < 2; kc++) {
            uint32_t a[2][4], bf[8][2], r4[4];
            ldsm4(a[0], ab + aofs + kc * 32);
            ldsm4(a[1], ab + 16 * 80 + aofs + kc * 32);
            #pragma unroll
            for (int q4 = 0; q4 < 4; q4++) {
                ldsm4(r4, bb + q4 * 16 * 80 + bofs + kc * 32);
                bf[q4 * 2][0] = r4[0]; bf[q4 * 2][1] = r4[1];
                bf[q4 * 2 + 1][0] = r4[2]; bf[q4 * 2 + 1][1] = r4[3];
            }
            #pragma unroll
            for (int mi = 0; mi < 2; mi++)
                #pragma unroll
                for (int ni = 0; ni < 8; ni++)
                    mma_f16(acc[mi][ni], a[mi], bf[ni]);
        }
    }

    #pragma unroll
    for (int mi = 0; mi < 2; mi++)
        #pragma unroll
        for (int rh = 0; rh < 2; rh++) {
            int m = m0 + warp_m * 32 + mi * 16 + rh * 8 + g;
            int r = m >> 9, s = m & 511;
            #pragma unroll
            for (int ni = 0; ni < 8; ni++) {
                int n = n0 + warp_n * 64 + ni * 8 + 2 * tig;
                float2 v;
                v.x = acc[mi][ni][rh * 2]     + bfv[n];
                v.y = acc[mi][ni][rh * 2 + 1] + bfv[n + 1];
                *(float2*)&out[((size_t)(s << 7) + r) * C_ + n] = v;
            }
        }
}

// ---------------------------------------------------------------------------
extern "C" void kernel_launch(void* const* d_in, const int* in_sizes, int n_in,
                              void* d_out, int out_size) {
    const float* x1d  = (const float*)d_in[0];
    const float* ln_w = (const float*)d_in[1];
    const float* ln_b = (const float*)d_in[2];
    const float* wq   = (const float*)d_in[3];
    const float* wk   = (const float*)d_in[4];
    const float* wv   = (const float*)d_in[5];
    const float* wg   = (const float*)d_in[6];
    const float* bg   = (const float*)d_in[7];
    const float* wf   = (const float*)d_in[8];
    const float* bf   = (const float*)d_in[9];
    float* out = (float*)d_out;

    cudaFuncSetAttribute(proj_gemm, cudaFuncAttributeMaxDynamicSharedMemorySize, GEMM_SMEM);
    cudaFuncSetAttribute(attn_mma,  cudaFuncAttributeMaxDynamicSharedMemorySize, ATTN_SMEM);
    cudaFuncSetAttribute(out_gemm,  cudaFuncAttributeMaxDynamicSharedMemorySize, GEMM_SMEM);

    prep_w<<<dim3(8, 8, 5), 256>>>(wq, wk, wv, wg, wf);
    ln_kernel<<<M_, 256>>>(x1d, ln_w, ln_b);
    proj_gemm<<<dim3(M_ / 128, 8), 256, GEMM_SMEM>>>(bg);
    attn_mma<<<dim3(2, 8, 128), 256, ATTN_SMEM>>>();
    out_gemm<<<dim3(M_ / 128, 2), 256, GEMM_SMEM>>>(bf, out);
}

// round 16
// speedup vs baseline: 1.0301x; 1.0301x over previous
#include <cuda_runtime.h>
#include <cuda_fp16.h>
#include <math.h>
#include <stdint.h>

#define S_ 512
#define R_ 128
#define C_ 256
#define H_ 8
#define DH_ 32
#define M_ (R_*S_)
#define EPSV 1e-5f
#define QSCALE 0.2550348923f   // (1/sqrt(32)) * log2(e), folded into q

__device__ __align__(256) __half g_xn16[(size_t)M_ * C_];   // ln out, [r][s][c]
__device__ __align__(256) __half g_q16[(size_t)M_ * C_];    // pre-scaled by QSCALE
__device__ __align__(256) __half g_k16[(size_t)M_ * C_];
__device__ __align__(256) __half g_v16[(size_t)M_ * C_];    // [r][s][h*32+dh]
__device__ __align__(256) __half g_oat16[(size_t)M_ * C_];  // gated attn out
__device__ __align__(256) __half g_gate16[(size_t)M_ * C_]; // sigmoid gate, fp16
__device__ __align__(256) __half g_w16[5 * 65536];          // W^T (n-major) fp16

// ---------------------------------------------------------------------------
// helpers
// ---------------------------------------------------------------------------
__device__ __forceinline__ void mma_f16(float* c, const uint32_t* a, const uint32_t* b) {
    asm volatile(
        "mma.sync.aligned.m16n8k16.row.col.f32.f16.f16.f32 "
        "{%0,%1,%2,%3}, {%4,%5,%6,%7}, {%8,%9}, {%0,%1,%2,%3};\n"
        : "+f"(c[0]), "+f"(c[1]), "+f"(c[2]), "+f"(c[3])
        : "r"(a[0]), "r"(a[1]), "r"(a[2]), "r"(a[3]), "r"(b[0]), "r"(b[1]));
}
__device__ __forceinline__ void ldsm4(uint32_t* r, uint32_t addr) {
    asm volatile("ldmatrix.sync.aligned.m8n8.x4.shared.b16 {%0,%1,%2,%3}, [%4];"
        : "=r"(r[0]), "=r"(r[1]), "=r"(r[2]), "=r"(r[3]) : "r"(addr));
}
__device__ __forceinline__ void ldsm4t(uint32_t* r, uint32_t addr) {
    asm volatile("ldmatrix.sync.aligned.m8n8.x4.trans.shared.b16 {%0,%1,%2,%3}, [%4];"
        : "=r"(r[0]), "=r"(r[1]), "=r"(r[2]), "=r"(r[3]) : "r"(addr));
}
__device__ __forceinline__ uint32_t packh2(float lo, float hi) {
    __half2 h = __floats2half2_rn(lo, hi);
    return *reinterpret_cast<uint32_t*>(&h);
}
__device__ __forceinline__ uint32_t h2ex2(uint32_t x) {
    uint32_t r; asm("ex2.approx.f16x2 %0, %1;" : "=r"(r) : "r"(x)); return r;
}
__device__ __forceinline__ uint32_t smaddr(const void* p) {
    return (uint32_t)__cvta_generic_to_shared(p);
}
__device__ __forceinline__ void cpa16(uint32_t s, const void* g) {
    asm volatile("cp.async.cg.shared.global [%0], [%1], 16;\n" :: "r"(s), "l"(g));
}
__device__ __forceinline__ void cpa_commit() { asm volatile("cp.async.commit_group;\n"); }
template<int N> __device__ __forceinline__ void cpa_wait() {
    asm volatile("cp.async.wait_group %0;\n" :: "n"(N));
}

// ---------------------------------------------------------------------------
// Weight prep: transpose 5 weight matrices to [n][k] fp16
// ---------------------------------------------------------------------------
__global__ __launch_bounds__(256) void prep_w(const float* __restrict__ wq,
                                              const float* __restrict__ wk,
                                              const float* __restrict__ wv,
                                              const float* __restrict__ wg,
                                              const float* __restrict__ wf) {
    __shared__ float tile[32][33];
    const float* s;
    switch (blockIdx.z) {
        case 0: s = wq; break;
        case 1: s = wk; break;
        case 2: s = wv; break;
        case 3: s = wg; break;
        default: s = wf; break;
    }
    int km = blockIdx.x * 32, nm = blockIdx.y * 32;
    int t = threadIdx.x, tr = t >> 5, tc = t & 31;
    #pragma unroll
    for (int p = 0; p < 4; p++)
        tile[tr + p * 8][tc] = s[(size_t)(km + tr + p * 8) * C_ + nm + tc];
    __syncthreads();
    #pragma unroll
    for (int p = 0; p < 4; p++) {
        int n = tr + p * 8;
        g_w16[(size_t)blockIdx.z * 65536 + (size_t)(nm + n) * C_ + km + tc] =
            __float2half_rn(tile[tc][n]);
    }
}

// ---------------------------------------------------------------------------
// LayerNorm over C + transpose [s][r][c] -> [r][s][c], store fp16
// ---------------------------------------------------------------------------
__global__ __launch_bounds__(256) void ln_kernel(const float* __restrict__ x,
                                                 const float* __restrict__ w,
                                                 const float* __restrict__ b) {
    int sr = blockIdx.x;
    int s = sr >> 7;
    int r = sr & 127;
    int t = threadIdx.x;
    float v = x[(size_t)sr * C_ + t];
    float sum = v, sq = v * v;
    #pragma unroll
    for (int o = 16; o > 0; o >>= 1) {
        sum += __shfl_xor_sync(0xffffffffu, sum, o);
        sq  += __shfl_xor_sync(0xffffffffu, sq,  o);
    }
    __shared__ float rs[8], rq[8];
    __shared__ float s_mu, s_rstd;
    int wid = t >> 5, lid = t & 31;
    if (lid == 0) { rs[wid] = sum; rq[wid] = sq; }
    __syncthreads();
    if (t == 0) {
        float a = 0.f, c2 = 0.f;
        #pragma unroll
        for (int i = 0; i < 8; i++) { a += rs[i]; c2 += rq[i]; }
        float mu  = a * (1.0f / C_);
        float var = c2 * (1.0f / C_) - mu * mu;
        s_mu = mu; s_rstd = rsqrtf(var + EPSV);
    }
    __syncthreads();
    g_xn16[((size_t)r * S_ + s) * C_ + t] =
        __float2half_rn((v - s_mu) * s_rstd * w[t] + b[t]);
}

// ---------------------------------------------------------------------------
// fp16 GEMM, 3-stage cp.async, ldmatrix fragments:
// g_xn16[M_,256] @ W^T -> q|k|v (fp16) / gate (fp16). 128x128, BK=32, 8 warps.
// q is pre-scaled by QSCALE so attention logits are already in log2 domain.
// ---------------------------------------------------------------------------
#define ASH 5120                     // 128*40 halves per stage
#define GEMM_SMEM (3 * 2 * ASH * 2)  // 61440 bytes

__global__ __launch_bounds__(256) void proj_gemm(const float* __restrict__ bg) {
    extern __shared__ __half smh[];
    __half* As = smh;                // [3][128][40]
    __half* Bs = smh + 3 * ASH;      // [3][128][40]
    const int tid = threadIdx.x;
    const int wid = tid >> 5, lane = tid & 31, g = lane >> 2, tig = lane & 3;
    const int warp_m = wid & 3, warp_n = wid >> 2;
    const int lm = lane >> 3, lr = lane & 7;
    const uint32_t aofs = (((lm & 1) * 8 + lr) * 40 + (lm >> 1) * 8) * 2;
    const uint32_t bofs = (((lm >> 1) * 8 + lr) * 40 + (lm & 1) * 8) * 2;
    const int m0 = blockIdx.x * 128;
    const int y = blockIdx.y;
    const int widx = y >> 1;
    const __half* Wp = g_w16 + (size_t)widx * 65536;
    const int n0w = (y & 1) * 128;

    float acc[2][8][4] = {};

    auto issue = [&](int st, int k0) {
        #pragma unroll
        for (int p = 0; p < 2; p++) {
            int idx = p * 256 + tid;
            int row = idx >> 2, c = idx & 3;
            cpa16(smaddr(&As[st * ASH + row * 40 + c * 8]),
                  &g_xn16[(size_t)(m0 + row) * C_ + k0 + c * 8]);
            cpa16(smaddr(&Bs[st * ASH + row * 40 + c * 8]),
                  &Wp[(size_t)(n0w + row) * C_ + k0 + c * 8]);
        }
        cpa_commit();
    };
    issue(0, 0); issue(1, 32);

    for (int it = 0; it < 8; it++) {
        if (it < 7) cpa_wait<1>(); else cpa_wait<0>();
        __syncthreads();
        if (it < 6) issue((it + 2) % 3, (it + 2) * 32);
        uint32_t ab = smaddr(&As[(it % 3) * ASH]) + warp_m * 32 * 80;
        uint32_t bb = smaddr(&Bs[(it % 3) * ASH]) + warp_n * 64 * 80;
        #pragma unroll
        for (int kc = 0; kc < 2; kc++) {
            uint32_t a[2][4], bf[8][2], r4[4];
            ldsm4(a[0], ab + aofs + kc * 32);
            ldsm4(a[1], ab + 16 * 80 + aofs + kc * 32);
            #pragma unroll
            for (int q4 = 0; q4 < 4; q4++) {
                ldsm4(r4, bb + q4 * 16 * 80 + bofs + kc * 32);
                bf[q4 * 2][0] = r4[0]; bf[q4 * 2][1] = r4[1];
                bf[q4 * 2 + 1][0] = r4[2]; bf[q4 * 2 + 1][1] = r4[3];
            }
            #pragma unroll
            for (int mi = 0; mi < 2; mi++)
                #pragma unroll
                for (int ni = 0; ni < 8; ni++)
                    mma_f16(acc[mi][ni], a[mi], bf[ni]);
        }
    }

    __half* dsth = (widx == 0) ? g_q16 : (widx == 1) ? g_k16 : g_v16;
    #pragma unroll
    for (int mi = 0; mi < 2; mi++)
        #pragma unroll
        for (int rh = 0; rh < 2; rh++) {
            int m = m0 + warp_m * 32 + mi * 16 + rh * 8 + g;
            #pragma unroll
            for (int ni = 0; ni < 8; ni++) {
                int ng = n0w + warp_n * 64 + ni * 8 + 2 * tig;
                float vx = acc[mi][ni][rh * 2], vy = acc[mi][ni][rh * 2 + 1];
                if (widx == 3) {
                    float gx = 1.f / (1.f + __expf(-(vx + bg[ng])));
                    float gy = 1.f / (1.f + __expf(-(vy + bg[ng + 1])));
                    *(uint32_t*)&g_gate16[(size_t)m * C_ + ng] = packh2(gx, gy);
                } else {
                    if (widx == 0) { vx *= QSCALE; vy *= QSCALE; }
                    *(uint32_t*)&dsth[(size_t)m * C_ + ng] = packh2(vx, vy);
                }
            }
        }
}

// ---------------------------------------------------------------------------
// Flash attention, fp16 m16n8k16. 256 queries/block, 8 warps, 4-stage
// cp.async K/V ring (3 tiles in flight). Max-free log2-domain softmax via
// ex2.approx.f16x2; P in registers; V^T fragments via ldmatrix.trans.
// ---------------------------------------------------------------------------
#define KVH 1280    // 32*40 halves per stage
#define QH  10240   // 256*40 halves
#define ATTN_SMEM ((QH + 8 * KVH) * 2)   // 40960 bytes

__global__ __launch_bounds__(256) void attn_mma() {
    extern __shared__ __half smh[];
    __half* Qs = smh;                 // [256][40]
    __half* Ks = smh + QH;            // [4][32][40]  rows j, cols dh
    __half* Vs = Ks + 4 * KVH;        // [4][32][40]  rows j, cols dh
    const int qt = blockIdx.x;        // 0..1
    const int h  = blockIdx.y;
    const int r  = blockIdx.z;
    const int tid = threadIdx.x, wid = tid >> 5, lane = tid & 31;
    const int g = lane >> 2, tig = lane & 3;
    const int lm = lane >> 3, lr = lane & 7;
    const uint32_t kofs = (((lm >> 1) * 8 + lr) * 40 + (lm & 1) * 8) * 2;
    const uint32_t vofs = (((lm & 1) * 8 + lr) * 40 + (lm >> 1) * 8) * 2;
    const size_t rbase = (size_t)r * S_;

    // 256 threads: tid<128 loads K tile (128 x 16B), tid>=128 loads V tile.
    const int irow = (tid & 127) >> 2, ic = tid & 3;
    auto issue = [&](int st, int j0) {
        if (tid < 128)
            cpa16(smaddr(&Ks[st * KVH + irow * 40 + ic * 8]),
                  &g_k16[(rbase + j0 + irow) * C_ + h * 32 + ic * 8]);
        else
            cpa16(smaddr(&Vs[st * KVH + irow * 40 + ic * 8]),
                  &g_v16[(rbase + j0 + irow) * C_ + h * 32 + ic * 8]);
        cpa_commit();
    };
    issue(0, 0); issue(1, 32); issue(2, 64);

    // Stage Q (256 rows), hoist fragments to registers
    #pragma unroll
    for (int p = 0; p < 4; p++) {
        int linear = p * 256 + tid;
        int row = linear >> 2, c = linear & 3;
        *(uint4*)&Qs[row * 40 + c * 8] =
            *(const uint4*)&g_q16[(rbase + qt * 256 + row) * C_ + h * 32 + c * 8];
    }
    __syncthreads();
    uint32_t qf[2][2][4];                      // [kc][mi]
    {
        uint32_t qb = smaddr(Qs) + wid * 32 * 80;
        const uint32_t qaofs = (((lm & 1) * 8 + lr) * 40 + (lm >> 1) * 8) * 2;
        #pragma unroll
        for (int kc = 0; kc < 2; kc++) {
            ldsm4(qf[kc][0], qb + qaofs + kc * 32);
            ldsm4(qf[kc][1], qb + 16 * 80 + qaofs + kc * 32);
        }
    }

    float lpart[2][2] = {};
    float oacc[2][4][4] = {};
    const uint32_t ksb = smaddr(Ks), vsb = smaddr(Vs);

    for (int t = 0; t < 16; t++) {
        if (t < 14) cpa_wait<2>(); else if (t == 14) cpa_wait<1>(); else cpa_wait<0>();
        __syncthreads();
        if (t < 13) issue((t + 3) & 3, (t + 3) * 32);
        uint32_t kb = ksb + (t & 3) * (KVH * 2);
        uint32_t vb = vsb + (t & 3) * (KVH * 2);

        // S = Q . K^T  (32q x 32k per warp); sacc is already log2-domain
        float sacc[2][4][4] = {};
        #pragma unroll
        for (int kc = 0; kc < 2; kc++) {
            uint32_t bk[4][2], r4[4];
            ldsm4(r4, kb + kofs + kc * 32);
            bk[0][0] = r4[0]; bk[0][1] = r4[1]; bk[1][0] = r4[2]; bk[1][1] = r4[3];
            ldsm4(r4, kb + kofs + kc * 32 + 16 * 80);
            bk[2][0] = r4[0]; bk[2][1] = r4[1]; bk[3][0] = r4[2]; bk[3][1] = r4[3];
            #pragma unroll
            for (int mi = 0; mi < 2; mi++)
                #pragma unroll
                for (int ni = 0; ni < 4; ni++)
                    mma_f16(sacc[mi][ni], qf[kc][mi], bk[ni]);
        }

        // Max-free softmax: p = 2^x via ex2.approx.f16x2, straight into A frags.
        uint32_t pa[2][2][4];                  // [kc][mi]
        #pragma unroll
        for (int mi = 0; mi < 2; mi++) {
            __half2 tl0 = __float2half2_rn(0.f);
            __half2 tl1 = __float2half2_rn(0.f);
            #pragma unroll
            for (int ni = 0; ni < 4; ni++) {
                int kc = ni >> 1, i0 = (ni & 1) * 2;
                uint32_t p0 = h2ex2(packh2(sacc[mi][ni][0], sacc[mi][ni][1]));
                uint32_t p1 = h2ex2(packh2(sacc[mi][ni][2], sacc[mi][ni][3]));
                pa[kc][mi][i0]     = p0;
                pa[kc][mi][i0 + 1] = p1;
                tl0 = __hadd2(tl0, *reinterpret_cast<__half2*>(&p0));
                tl1 = __hadd2(tl1, *reinterpret_cast<__half2*>(&p1));
            }
            float2 f0 = __half22float2(tl0);
            float2 f1 = __half22float2(tl1);
            lpart[mi][0] += f0.x + f0.y;
            lpart[mi][1] += f1.x + f1.y;
        }

        // O += P . V   — V^T fragments via ldmatrix.trans from [j][dh] tile
        #pragma unroll
        for (int kc = 0; kc < 2; kc++) {
            uint32_t bv[4][2], r4[4];
            ldsm4t(r4, vb + vofs + kc * 1280);
            bv[0][0] = r4[0]; bv[0][1] = r4[1]; bv[1][0] = r4[2]; bv[1][1] = r4[3];
            ldsm4t(r4, vb + vofs + kc * 1280 + 32);
            bv[2][0] = r4[0]; bv[2][1] = r4[1]; bv[3][0] = r4[2]; bv[3][1] = r4[3];
            #pragma unroll
            for (int mi = 0; mi < 2; mi++)
                #pragma unroll
                for (int ni = 0; ni < 4; ni++)
                    mma_f16(oacc[mi][ni], pa[kc][mi], bv[ni]);
        }
    }

    #pragma unroll
    for (int mi = 0; mi < 2; mi++)
        #pragma unroll
        for (int rh = 0; rh < 2; rh++) {
            float ts = lpart[mi][rh];
            ts += __shfl_xor_sync(0xffffffffu, ts, 1);
            ts += __shfl_xor_sync(0xffffffffu, ts, 2);
            float inv = 1.f / ts;
            int q = qt * 256 + wid * 32 + mi * 16 + rh * 8 + g;
            #pragma unroll
            for (int ni = 0; ni < 4; ni++) {
                int n = ni * 8 + 2 * tig;
                uint32_t gbits = *(const uint32_t*)&g_gate16[(rbase + q) * C_ + h * 32 + n];
                float2 gg = __half22float2(*reinterpret_cast<__half2*>(&gbits));
                *(uint32_t*)&g_oat16[(rbase + q) * C_ + h * 32 + n] =
                    packh2(oacc[mi][ni][rh * 2] * inv * gg.x,
                           oacc[mi][ni][rh * 2 + 1] * inv * gg.y);
            }
        }
}

// ---------------------------------------------------------------------------
// fp16 GEMM: g_oat16 @ wf^T + bf, transposed store to out[s][r][c]
// ---------------------------------------------------------------------------
__global__ __launch_bounds__(256) void out_gemm(const float* __restrict__ bfv,
                                                float* __restrict__ out) {
    extern __shared__ __half smh[];
    __half* As = smh;
    __half* Bs = smh + 3 * ASH;
    const int tid = threadIdx.x;
    const int wid = tid >> 5, lane = tid & 31, g = lane >> 2, tig = lane & 3;
    const int warp_m = wid & 3, warp_n = wid >> 2;
    const int lm = lane >> 3, lr = lane & 7;
    const uint32_t aofs = (((lm & 1) * 8 + lr) * 40 + (lm >> 1) * 8) * 2;
    const uint32_t bofs = (((lm >> 1) * 8 + lr) * 40 + (lm & 1) * 8) * 2;
    const int m0 = blockIdx.x * 128;
    const int n0 = blockIdx.y * 128;
    const __half* Wp = g_w16 + (size_t)4 * 65536;

    float acc[2][8][4] = {};

    auto issue = [&](int st, int k0) {
        #pragma unroll
        for (int p = 0; p < 2; p++) {
            int idx = p * 256 + tid;
            int row = idx >> 2, c = idx & 3;
            cpa16(smaddr(&As[st * ASH + row * 40 + c * 8]),
                  &g_oat16[(size_t)(m0 + row) * C_ + k0 + c * 8]);
            cpa16(smaddr(&Bs[st * ASH + row * 40 + c * 8]),
                  &Wp[(size_t)(n0 + row) * C_ + k0 + c * 8]);
        }
        cpa_commit();
    };
    issue(0, 0); issue(1, 32);

    for (int it = 0; it < 8; it++) {
        if (it < 7) cpa_wait<1>(); else cpa_wait<0>();
        __syncthreads();
        if (it < 6) issue((it + 2) % 3, (it + 2) * 32);
        uint32_t ab = smaddr(&As[(it % 3) * ASH]) + warp_m * 32 * 80;
        uint32_t bb = smaddr(&Bs[(it % 3) * ASH]) + warp_n * 64 * 80;
        #pragma unroll
        for (int kc = 0; kc < 2; kc++) {
            uint32_t a[2][4], bf[8][2], r4[4];
            ldsm4(a[0], ab + aofs + kc * 32);
            ldsm4(a[1], ab + 16 * 80 + aofs + kc * 32);
            #pragma unroll
            for (int q4 = 0; q4 < 4; q4++) {
                ldsm4(r4, bb + q4 * 16 * 80 + bofs + kc * 32);
                bf[q4 * 2][0] = r4[0]; bf[q4 * 2][1] = r4[1];
                bf[q4 * 2 + 1][0] = r4[2]; bf[q4 * 2 + 1][1] = r4[3];
            }
            #pragma unroll
            for (int mi = 0; mi < 2; mi++)
                #pragma unroll
                for (int ni = 0; ni < 8; ni++)
                    mma_f16(acc[mi][ni], a[mi], bf[ni]);
        }
    }

    #pragma unroll
    for (int mi = 0; mi < 2; mi++)
        #pragma unroll
        for (int rh = 0; rh < 2; rh++) {
            int m = m0 + warp_m * 32 + mi * 16 + rh * 8 + g;
            int r = m >> 9, s = m & 511;
            #pragma unroll
            for (int ni = 0; ni < 8; ni++) {
                int n = n0 + warp_n * 64 + ni * 8 + 2 * tig;
                float2 v;
                v.x = acc[mi][ni][rh * 2]     + bfv[n];
                v.y = acc[mi][ni][rh * 2 + 1] + bfv[n + 1];
                *(float2*)&out[((size_t)(s << 7) + r) * C_ + n] = v;
            }
        }
}

// ---------------------------------------------------------------------------
extern "C" void kernel_launch(void* const* d_in, const int* in_sizes, int n_in,
                              void* d_out, int out_size) {
    const float* x1d  = (const float*)d_in[0];
    const float* ln_w = (const float*)d_in[1];
    const float* ln_b = (const float*)d_in[2];
    const float* wq   = (const float*)d_in[3];
    const float* wk   = (const float*)d_in[4];
    const float* wv   = (const float*)d_in[5];
    const float* wg   = (const float*)d_in[6];
    const float* bg   = (const float*)d_in[7];
    const float* wf   = (const float*)d_in[8];
    const float* bf   = (const float*)d_in[9];
    float* out = (float*)d_out;

    cudaFuncSetAttribute(proj_gemm, cudaFuncAttributeMaxDynamicSharedMemorySize, GEMM_SMEM);
    cudaFuncSetAttribute(attn_mma,  cudaFuncAttributeMaxDynamicSharedMemorySize, ATTN_SMEM);
    cudaFuncSetAttribute(out_gemm,  cudaFuncAttributeMaxDynamicSharedMemorySize, GEMM_SMEM);

    prep_w<<<dim3(8, 8, 5), 256>>>(wq, wk, wv, wg, wf);
    ln_kernel<<<M_, 256>>>(x1d, ln_w, ln_b);
    proj_gemm<<<dim3(M_ / 128, 8), 256, GEMM_SMEM>>>(bg);
    attn_mma<<<dim3(2, 8, 128), 256, ATTN_SMEM>>>();
    out_gemm<<<dim3(M_ / 128, 2), 256, GEMM_SMEM>>>(bf, out);
}